// round 13
// baseline (speedup 1.0000x reference)
#include <cuda_runtime.h>
#include <cstdint>

#define T_TOK 8192
#define IN_F  2048
#define OUT_F 2048
#define THRESH 6.0f
#define MAXOUT 64

// ---------------- device scratch ----------------
__device__ int8_t   g_wq[(size_t)OUT_F * IN_F];   // 4 MB
__device__ float    g_wscale[OUT_F];
__device__ int8_t   g_xq[(size_t)T_TOK * IN_F];   // 16 MB
__device__ float    g_xscale[T_TOK];
__device__ unsigned g_colmax[IN_F];
__device__ int      g_outidx[IN_F];
__device__ int      g_nout;
__device__ float    g_xout[(size_t)T_TOK * MAXOUT];   // 2 MB packed outlier x
__device__ float    g_wout[(size_t)OUT_F * MAXOUT];   // 512 KB packed outlier wq

// ---------------- prep kernels ----------------
__global__ void k_init() {
    int i = blockIdx.x * 256 + threadIdx.x;
    if (i < IN_F) g_colmax[i] = 0u;
}

__global__ void k_colmax(const float* __restrict__ x) {
    int c = blockIdx.x * 256 + threadIdx.x;
    const float* p = x + (size_t)blockIdx.y * 256 * IN_F + c;
    float m = 0.f;
#pragma unroll 4
    for (int r = 0; r < 256; ++r) m = fmaxf(m, fabsf(p[(size_t)r * IN_F]));
    atomicMax(&g_colmax[c], __float_as_uint(m));
}

__device__ __forceinline__ float block_reduce_max(float v, float* sh) {
#pragma unroll
    for (int o = 16; o > 0; o >>= 1) v = fmaxf(v, __shfl_xor_sync(0xffffffffu, v, o));
    int w = threadIdx.x >> 5;
    if ((threadIdx.x & 31) == 0) sh[w] = v;
    __syncthreads();
    float r = sh[0];
#pragma unroll
    for (int i = 1; i < 8; ++i) r = fmaxf(r, sh[i]);
    return r;
}

__global__ void k_quantw(const float* __restrict__ w) {
    __shared__ float sh[8];
    int row = blockIdx.x;
    const float* wr = w + (size_t)row * IN_F;
    float v[8]; float m = 0.f;
#pragma unroll
    for (int i = 0; i < 8; ++i) { v[i] = wr[threadIdx.x + i * 256]; m = fmaxf(m, fabsf(v[i])); }
    float amax = fmaxf(block_reduce_max(m, sh), 1e-6f);
    float s = 127.0f / amax;
#pragma unroll
    for (int i = 0; i < 8; ++i) {
        float q = rintf(v[i] * s);
        q = fminf(fmaxf(q, -127.f), 127.f);
        g_wq[(size_t)row * IN_F + threadIdx.x + i * 256] = (int8_t)q;
    }
    if (threadIdx.x == 0) g_wscale[row] = amax / 127.0f;
}

// fast deterministic gather: 2048-bit outlier mask + popc prefix ranks
__global__ void k_gather3() {
    __shared__ uint32_t mask[64];
    __shared__ int wpref[64];
    int tid = threadIdx.x, lane = tid & 31, w = tid >> 5;   // 8 warps
#pragma unroll
    for (int it = 0; it < 8; ++it) {
        int wi = it * 8 + w;
        bool f = __uint_as_float(g_colmax[wi * 32 + lane]) > THRESH;
        uint32_t m = __ballot_sync(0xffffffffu, f);
        if (lane == 0) mask[wi] = m;
    }
    __syncthreads();
    if (tid < 64) {
        int s = 0;
        for (int k = 0; k < tid; ++k) s += __popc(mask[k]);
        wpref[tid] = s;
    }
    __syncthreads();
#pragma unroll
    for (int it = 0; it < 8; ++it) {
        int c = it * 256 + tid;
        uint32_t m = mask[c >> 5];
        if (m & (1u << (c & 31))) {
            int r = wpref[c >> 5] + __popc(m & ((1u << (c & 31)) - 1u));
            g_outidx[r] = c;
        }
    }
    if (tid == 0) g_nout = wpref[63] + __popc(mask[63]);
}

// pack outlier columns of x and wq into padded [.,64] arrays (zero-filled)
__global__ void k_pack(const float* __restrict__ x) {
    int idx = blockIdx.x * 256 + threadIdx.x;
    int nout = g_nout; if (nout > MAXOUT) nout = MAXOUT;
    if (idx < T_TOK * MAXOUT) {
        int t = idx >> 6, s = idx & 63;
        float v = 0.f;
        if (s < nout) v = x[(size_t)t * IN_F + g_outidx[s]];
        g_xout[idx] = v;
    } else {
        int j = idx - T_TOK * MAXOUT;
        int o = j >> 6, s = j & 63;
        float v = 0.f;
        if (s < nout) v = (float)g_wq[(size_t)o * IN_F + g_outidx[s]];
        g_wout[j] = v;
    }
}

__global__ void k_quantx(const float* __restrict__ x) {
    __shared__ float sh[8];
    int t = blockIdx.x;
    const float* xr = x + (size_t)t * IN_F;
    float v[8]; float m = 0.f;
#pragma unroll
    for (int i = 0; i < 8; ++i) {
        int c = threadIdx.x + i * 256;
        float f = xr[c];
        if (__uint_as_float(g_colmax[c]) > THRESH) f = 0.f;
        v[i] = f;
        m = fmaxf(m, fabsf(f));
    }
    float amax = fmaxf(block_reduce_max(m, sh), 1e-6f);
    float s = 127.0f / amax;
#pragma unroll
    for (int i = 0; i < 8; ++i) {
        float q = rintf(v[i] * s);
        q = fminf(fmaxf(q, -127.f), 127.f);
        g_xq[(size_t)t * IN_F + threadIdx.x + i * 256] = (int8_t)q;
    }
    if (threadIdx.x == 0) g_xscale[t] = amax / 127.0f;
}

// ---------------- DP4A GEMM: BM=128, BN=64, BK=128, cp.async 2-stage, SW128 ----------------
// 2048 CTAs -> 6.92 waves at 2 CTA/SM (98.9% wave packing).
// 256 threads, microtile 8x4. SMEM: A[2][16KB] at 0, B[2][8KB] at 32768.
#define NTILES 16     // 2048 / 128

__device__ __forceinline__ uint32_t swz128(uint32_t off) { return off ^ ((off >> 3) & 0x70); }

__device__ __forceinline__ uint32_t smem_u32(const void* p) {
    uint32_t a;
    asm("{ .reg .u64 t; cvta.to.shared.u64 t, %1; cvt.u32.u64 %0, t; }" : "=r"(a) : "l"(p));
    return a;
}
__device__ __forceinline__ void cpa16(uint32_t dst, const void* src) {
    asm volatile("cp.async.cg.shared.global [%0], [%1], 16;" :: "r"(dst), "l"(src));
}
#define CP_COMMIT() asm volatile("cp.async.commit_group;" ::: "memory")
#define CP_WAIT0()  asm volatile("cp.async.wait_group 0;" ::: "memory")

__device__ __forceinline__ int dp4(uint32_t a, uint32_t b, int c) {
    return __dp4a((int)a, (int)b, c);
}

__global__ __launch_bounds__(256, 2) void k_gemm(const float* __restrict__ bias,
                                                 float* __restrict__ out) {
    extern __shared__ char sm[];
    const uint32_t sbase = smem_u32(sm);
    const int tid = threadIdx.x;
    const int tx = tid & 15;          // n dir: cols tx + j*16, j<4
    const int ty = tid >> 4;          // m dir: rows ty*8 + i, i<8
    const int m_blk = blockIdx.y * 128;
    const int n_blk = blockIdx.x * 64;

    const int lrow = tid >> 3;        // 0..31
    const int lq = tid & 7;
    const uint32_t sto = swz128((uint32_t)(lrow * 128 + lq * 16));

    int acc[8][4];
#pragma unroll
    for (int i = 0; i < 8; ++i)
#pragma unroll
        for (int j = 0; j < 4; ++j) acc[i][j] = 0;

    // ---- preload tile 0 ----
    {
        const int8_t* ga = g_xq + (size_t)(m_blk + lrow) * IN_F + lq * 16;
        const int8_t* gb = g_wq + (size_t)(n_blk + lrow) * IN_F + lq * 16;
#pragma unroll
        for (int i = 0; i < 4; ++i)
            cpa16(sbase + sto + i * (32 * 128), ga + (size_t)i * 32 * IN_F);
#pragma unroll
        for (int i = 0; i < 2; ++i)
            cpa16(sbase + 32768 + sto + i * (32 * 128), gb + (size_t)i * 32 * IN_F);
        CP_COMMIT(); CP_WAIT0();
    }
    __syncthreads();

#pragma unroll 1
    for (int t = 0; t < NTILES; ++t) {
        const int buf = t & 1;
        const bool more = (t + 1) < NTILES;
        if (more) {
            const int nb = buf ^ 1;
            const size_t kof = (size_t)(t + 1) * 128 + lq * 16;
            const int8_t* ga = g_xq + (size_t)(m_blk + lrow) * IN_F + kof;
            const int8_t* gb = g_wq + (size_t)(n_blk + lrow) * IN_F + kof;
#pragma unroll
            for (int i = 0; i < 4; ++i)
                cpa16(sbase + nb * 16384 + sto + i * (32 * 128), ga + (size_t)i * 32 * IN_F);
#pragma unroll
            for (int i = 0; i < 2; ++i)
                cpa16(sbase + 32768 + nb * 8192 + sto + i * (32 * 128), gb + (size_t)i * 32 * IN_F);
            CP_COMMIT();
        }
        const char* aS = sm + buf * 16384;
        const char* bS = sm + 32768 + buf * 8192;
#pragma unroll
        for (int kk = 0; kk < 8; ++kk) {
            uint4 bf[4];
#pragma unroll
            for (int j = 0; j < 4; ++j)
                bf[j] = *reinterpret_cast<const uint4*>(bS + swz128((uint32_t)((tx + j * 16) * 128 + kk * 16)));
#pragma unroll
            for (int i = 0; i < 8; ++i) {
                uint4 a = *reinterpret_cast<const uint4*>(aS + swz128((uint32_t)((ty * 8 + i) * 128 + kk * 16)));
#pragma unroll
                for (int j = 0; j < 4; ++j) {
                    acc[i][j] = dp4(a.x, bf[j].x, acc[i][j]);
                    acc[i][j] = dp4(a.y, bf[j].y, acc[i][j]);
                    acc[i][j] = dp4(a.z, bf[j].z, acc[i][j]);
                    acc[i][j] = dp4(a.w, bf[j].w, acc[i][j]);
                }
            }
        }
        if (more) CP_WAIT0();
        __syncthreads();
    }

    // ---- dequant + fp outlier epilogue ----
    float xs[8], ws[4], bs[4];
#pragma unroll
    for (int i = 0; i < 8; ++i) xs[i] = g_xscale[m_blk + ty * 8 + i];
#pragma unroll
    for (int j = 0; j < 4; ++j) {
        int gn = n_blk + tx + j * 16;
        ws[j] = g_wscale[gn];
        bs[j] = bias[gn];
    }

    float facc[8][4];
#pragma unroll
    for (int i = 0; i < 8; ++i)
#pragma unroll
        for (int j = 0; j < 4; ++j) facc[i][j] = xs[i] * (float)acc[i][j];

    float* xo = reinterpret_cast<float*>(sm);            // [128][17]
    float* wo = reinterpret_cast<float*>(sm + 8704);     // [64][17]

    int nout = g_nout; if (nout > MAXOUT) nout = MAXOUT;
    for (int base = 0; base < nout; base += 16) {
        for (int idx = tid; idx < 192 * 16; idx += 256) {
            if (idx < 128 * 16) {
                int r = idx >> 4, c = idx & 15;
                xo[r * 17 + c] = g_xout[(size_t)(m_blk + r) * MAXOUT + base + c];
            } else {
                int j2 = idx - 128 * 16;
                int r = j2 >> 4, c = j2 & 15;
                wo[r * 17 + c] = g_wout[(size_t)(n_blk + r) * MAXOUT + base + c];
            }
        }
        __syncthreads();
#pragma unroll
        for (int c = 0; c < 16; ++c) {
            float xa[8], wb[4];
#pragma unroll
            for (int i = 0; i < 8; ++i) xa[i] = xo[(ty * 8 + i) * 17 + c];
#pragma unroll
            for (int j = 0; j < 4; ++j) wb[j] = wo[(tx + j * 16) * 17 + c];
#pragma unroll
            for (int i = 0; i < 8; ++i)
#pragma unroll
                for (int j = 0; j < 4; ++j) facc[i][j] += xa[i] * wb[j];
        }
        __syncthreads();
    }

#pragma unroll
    for (int i = 0; i < 8; ++i) {
        size_t gm = m_blk + ty * 8 + i;
#pragma unroll
        for (int j = 0; j < 4; ++j) {
            int gn = n_blk + tx + j * 16;
            out[gm * OUT_F + gn] = ws[j] * facc[i][j] + bs[j];
        }
    }
}

// ---------------- launch ----------------
extern "C" void kernel_launch(void* const* d_in, const int* in_sizes, int n_in,
                              void* d_out, int out_size) {
    const float* x    = (const float*)d_in[0];
    const float* w    = (const float*)d_in[1];
    const float* bias = (const float*)d_in[2];
    float* out = (float*)d_out;

    cudaFuncSetAttribute(k_gemm, cudaFuncAttributeMaxDynamicSharedMemorySize, 49152);

    k_init<<<8, 256>>>();
    k_colmax<<<dim3(IN_F / 256, 32), 256>>>(x);
    k_quantw<<<OUT_F, 256>>>(w);
    k_gather3<<<1, 256>>>();
    k_pack<<<(T_TOK + OUT_F) * MAXOUT / 256, 256>>>(x);
    k_quantx<<<T_TOK, 256>>>(x);
    k_gemm<<<dim3(OUT_F / 64, T_TOK / 128), 256, 49152>>>(bias, out);
}

// round 14
// speedup vs baseline: 1.0206x; 1.0206x over previous
#include <cuda_runtime.h>
#include <cstdint>

#define T_TOK 8192
#define IN_F  2048
#define OUT_F 2048
#define THRESH 6.0f
#define MAXOUT 64

// ---------------- device scratch ----------------
__device__ int8_t   g_wq[(size_t)OUT_F * IN_F];   // 4 MB
__device__ float    g_wscale[OUT_F];
__device__ int8_t   g_xq[(size_t)T_TOK * IN_F];   // 16 MB
__device__ float    g_xscale[T_TOK];
__device__ unsigned g_colmax[IN_F];
__device__ int      g_outidx[IN_F];
__device__ int      g_colrank[IN_F];
__device__ int      g_nout;
__device__ float    g_xout[(size_t)T_TOK * MAXOUT];   // 2 MB packed outlier x
__device__ float    g_wout[(size_t)OUT_F * MAXOUT];   // 512 KB packed outlier wq

// ---------------- prep ----------------
__global__ void k_init() {
    int i = blockIdx.x * 256 + threadIdx.x;
    if (i < IN_F) g_colmax[i] = 0u;
}

__device__ __forceinline__ float block_reduce_max(float v, float* sh) {
#pragma unroll
    for (int o = 16; o > 0; o >>= 1) v = fmaxf(v, __shfl_xor_sync(0xffffffffu, v, o));
    int w = threadIdx.x >> 5;
    if ((threadIdx.x & 31) == 0) sh[w] = v;
    __syncthreads();
    float r = sh[0];
#pragma unroll
    for (int i = 1; i < 8; ++i) r = fmaxf(r, sh[i]);
    return r;
}

// fused: blocks [0,256) column absmax of x; blocks [256,2304) row quant of w
__global__ void k_cq(const float* __restrict__ x, const float* __restrict__ w) {
    __shared__ float sh[8];
    const int tid = threadIdx.x;
    if (blockIdx.x < 256) {
        int c = (blockIdx.x & 7) * 256 + tid;
        const float* p = x + (size_t)(blockIdx.x >> 3) * 256 * IN_F + c;
        float m = 0.f;
#pragma unroll 4
        for (int r = 0; r < 256; ++r) m = fmaxf(m, fabsf(p[(size_t)r * IN_F]));
        atomicMax(&g_colmax[c], __float_as_uint(m));
    } else {
        int row = blockIdx.x - 256;
        const float* wr = w + (size_t)row * IN_F;
        float v[8]; float m = 0.f;
#pragma unroll
        for (int i = 0; i < 8; ++i) { v[i] = wr[tid + i * 256]; m = fmaxf(m, fabsf(v[i])); }
        float amax = fmaxf(block_reduce_max(m, sh), 1e-6f);
        float s = 127.0f / amax;
#pragma unroll
        for (int i = 0; i < 8; ++i) {
            float q = rintf(v[i] * s);
            q = fminf(fmaxf(q, -127.f), 127.f);
            g_wq[(size_t)row * IN_F + tid + i * 256] = (int8_t)q;
        }
        if (tid == 0) g_wscale[row] = amax / 127.0f;
    }
}

// deterministic gather: 2048-bit mask + popc prefix ranks; also records colrank
__global__ void k_gather3() {
    __shared__ uint32_t mask[64];
    __shared__ int wpref[64];
    int tid = threadIdx.x, lane = tid & 31, w = tid >> 5;
#pragma unroll
    for (int it = 0; it < 8; ++it) {
        int wi = it * 8 + w;
        bool f = __uint_as_float(g_colmax[wi * 32 + lane]) > THRESH;
        uint32_t m = __ballot_sync(0xffffffffu, f);
        if (lane == 0) mask[wi] = m;
    }
    __syncthreads();
    if (tid < 64) {
        int s = 0;
        for (int k = 0; k < tid; ++k) s += __popc(mask[k]);
        wpref[tid] = s;
    }
    __syncthreads();
#pragma unroll
    for (int it = 0; it < 8; ++it) {
        int c = it * 256 + tid;
        uint32_t m = mask[c >> 5];
        if (m & (1u << (c & 31))) {
            int r = wpref[c >> 5] + __popc(m & ((1u << (c & 31)) - 1u));
            g_outidx[r] = c;
            g_colrank[c] = r;
        }
    }
    if (tid == 0) g_nout = wpref[63] + __popc(mask[63]);
}

// fused: blocks [0,8192) quantx + pack own token's outlier row; blocks [8192,8704) pack w
__global__ void k_qp(const float* __restrict__ x) {
    __shared__ float sh[8];
    const int tid = threadIdx.x;
    if (blockIdx.x < T_TOK) {
        const int t = blockIdx.x;
        const float* xr = x + (size_t)t * IN_F;
        if (tid < MAXOUT) g_xout[(size_t)t * MAXOUT + tid] = 0.f;
        __syncthreads();
        float v[8]; float m = 0.f;
#pragma unroll
        for (int i = 0; i < 8; ++i) {
            int c = tid + i * 256;
            float f = xr[c];
            if (__uint_as_float(g_colmax[c]) > THRESH) {
                int r = g_colrank[c];
                if (r < MAXOUT) g_xout[(size_t)t * MAXOUT + r] = f;
                f = 0.f;
            }
            v[i] = f;
            m = fmaxf(m, fabsf(f));
        }
        float amax = fmaxf(block_reduce_max(m, sh), 1e-6f);
        float s = 127.0f / amax;
#pragma unroll
        for (int i = 0; i < 8; ++i) {
            float q = rintf(v[i] * s);
            q = fminf(fmaxf(q, -127.f), 127.f);
            g_xq[(size_t)t * IN_F + tid + i * 256] = (int8_t)q;
        }
        if (tid == 0) g_xscale[t] = amax / 127.0f;
    } else {
        int j = (blockIdx.x - T_TOK) * 256 + tid;     // [0, OUT_F*64)
        int o = j >> 6, s = j & 63;
        int nout = g_nout; if (nout > MAXOUT) nout = MAXOUT;
        float v = 0.f;
        if (s < nout) v = (float)g_wq[(size_t)o * IN_F + g_outidx[s]];
        g_wout[j] = v;
    }
}

// ---------------- DP4A GEMM: BM=BN=128, BK=128, cp.async 2-stage, SW128 (proven R9) ----------------
#define NTILES 16

__device__ __forceinline__ uint32_t swz128(uint32_t off) { return off ^ ((off >> 3) & 0x70); }

__device__ __forceinline__ uint32_t smem_u32(const void* p) {
    uint32_t a;
    asm("{ .reg .u64 t; cvta.to.shared.u64 t, %1; cvt.u32.u64 %0, t; }" : "=r"(a) : "l"(p));
    return a;
}
__device__ __forceinline__ void cpa16(uint32_t dst, const void* src) {
    asm volatile("cp.async.cg.shared.global [%0], [%1], 16;" :: "r"(dst), "l"(src));
}
#define CP_COMMIT() asm volatile("cp.async.commit_group;" ::: "memory")
#define CP_WAIT0()  asm volatile("cp.async.wait_group 0;" ::: "memory")

__device__ __forceinline__ int dp4(uint32_t a, uint32_t b, int c) {
    return __dp4a((int)a, (int)b, c);
}

__global__ __launch_bounds__(256, 2) void k_gemm(const float* __restrict__ bias,
                                                 float* __restrict__ out) {
    extern __shared__ char sm[];
    const uint32_t sbase = smem_u32(sm);
    const int tid = threadIdx.x;
    const int tx = tid & 15;
    const int ty = tid >> 4;
    const int m_blk = blockIdx.y * 128;
    const int n_blk = blockIdx.x * 128;

    const int lrow = tid >> 3;
    const int lq = tid & 7;
    const uint32_t sto = swz128((uint32_t)(lrow * 128 + lq * 16));

    int acc[8][8];
#pragma unroll
    for (int i = 0; i < 8; ++i)
#pragma unroll
        for (int j = 0; j < 8; ++j) acc[i][j] = 0;

    {
        const int8_t* ga = g_xq + (size_t)(m_blk + lrow) * IN_F + lq * 16;
        const int8_t* gb = g_wq + (size_t)(n_blk + lrow) * IN_F + lq * 16;
#pragma unroll
        for (int i = 0; i < 4; ++i) {
            cpa16(sbase + sto + i * (32 * 128),         ga + (size_t)i * 32 * IN_F);
            cpa16(sbase + 32768 + sto + i * (32 * 128), gb + (size_t)i * 32 * IN_F);
        }
        CP_COMMIT(); CP_WAIT0();
    }
    __syncthreads();

#pragma unroll 1
    for (int t = 0; t < NTILES; ++t) {
        const int buf = t & 1;
        const bool more = (t + 1) < NTILES;
        if (more) {
            const int nb = buf ^ 1;
            const size_t kof = (size_t)(t + 1) * 128 + lq * 16;
            const int8_t* ga = g_xq + (size_t)(m_blk + lrow) * IN_F + kof;
            const int8_t* gb = g_wq + (size_t)(n_blk + lrow) * IN_F + kof;
#pragma unroll
            for (int i = 0; i < 4; ++i) {
                cpa16(sbase + nb * 16384 + sto + i * (32 * 128),         ga + (size_t)i * 32 * IN_F);
                cpa16(sbase + 32768 + nb * 16384 + sto + i * (32 * 128), gb + (size_t)i * 32 * IN_F);
            }
            CP_COMMIT();
        }
        const char* aS = sm + buf * 16384;
        const char* bS = sm + 32768 + buf * 16384;
#pragma unroll
        for (int kk = 0; kk < 8; ++kk) {
            uint4 bf[8];
#pragma unroll
            for (int j = 0; j < 8; ++j)
                bf[j] = *reinterpret_cast<const uint4*>(bS + swz128((uint32_t)((tx + j * 16) * 128 + kk * 16)));
#pragma unroll
            for (int i = 0; i < 8; ++i) {
                uint4 a = *reinterpret_cast<const uint4*>(aS + swz128((uint32_t)((ty * 8 + i) * 128 + kk * 16)));
#pragma unroll
                for (int j = 0; j < 8; ++j) {
                    acc[i][j] = dp4(a.x, bf[j].x, acc[i][j]);
                    acc[i][j] = dp4(a.y, bf[j].y, acc[i][j]);
                    acc[i][j] = dp4(a.z, bf[j].z, acc[i][j]);
                    acc[i][j] = dp4(a.w, bf[j].w, acc[i][j]);
                }
            }
        }
        if (more) CP_WAIT0();
        __syncthreads();
    }

    float xs[8], ws[8], bs[8];
#pragma unroll
    for (int i = 0; i < 8; ++i) xs[i] = g_xscale[m_blk + ty * 8 + i];
#pragma unroll
    for (int j = 0; j < 8; ++j) {
        int gn = n_blk + tx + j * 16;
        ws[j] = g_wscale[gn];
        bs[j] = bias[gn];
    }

    float facc[8][8];
#pragma unroll
    for (int i = 0; i < 8; ++i)
#pragma unroll
        for (int j = 0; j < 8; ++j) facc[i][j] = xs[i] * (float)acc[i][j];

    float* xo = reinterpret_cast<float*>(sm);            // [128][17]
    float* wo = reinterpret_cast<float*>(sm + 8704);     // [128][17]

    int nout = g_nout; if (nout > MAXOUT) nout = MAXOUT;
    for (int base = 0; base < nout; base += 16) {
        for (int idx = tid; idx < 128 * 16; idx += 256) {
            int r = idx >> 4, c = idx & 15;
            xo[r * 17 + c] = g_xout[(size_t)(m_blk + r) * MAXOUT + base + c];
            wo[r * 17 + c] = g_wout[(size_t)(n_blk + r) * MAXOUT + base + c];
        }
        __syncthreads();
#pragma unroll
        for (int c = 0; c < 16; ++c) {
            float xa[8], wb[8];
#pragma unroll
            for (int i = 0; i < 8; ++i) xa[i] = xo[(ty * 8 + i) * 17 + c];
#pragma unroll
            for (int j = 0; j < 8; ++j) wb[j] = wo[(tx + j * 16) * 17 + c];
#pragma unroll
            for (int i = 0; i < 8; ++i)
#pragma unroll
                for (int j = 0; j < 8; ++j) facc[i][j] += xa[i] * wb[j];
        }
        __syncthreads();
    }

#pragma unroll
    for (int i = 0; i < 8; ++i) {
        size_t gm = m_blk + ty * 8 + i;
#pragma unroll
        for (int j = 0; j < 8; ++j) {
            int gn = n_blk + tx + j * 16;
            out[gm * OUT_F + gn] = ws[j] * facc[i][j] + bs[j];
        }
    }
}

// ---------------- launch ----------------
extern "C" void kernel_launch(void* const* d_in, const int* in_sizes, int n_in,
                              void* d_out, int out_size) {
    const float* x    = (const float*)d_in[0];
    const float* w    = (const float*)d_in[1];
    const float* bias = (const float*)d_in[2];
    float* out = (float*)d_out;

    cudaFuncSetAttribute(k_gemm, cudaFuncAttributeMaxDynamicSharedMemorySize, 65536);

    k_init<<<8, 256>>>();
    k_cq<<<256 + OUT_F, 256>>>(x, w);
    k_gather3<<<1, 256>>>();
    k_qp<<<T_TOK + OUT_F * MAXOUT / 256, 256>>>(x);
    k_gemm<<<dim3(OUT_F / 128, T_TOK / 128), 256, 65536>>>(bias, out);
}

// round 15
// speedup vs baseline: 1.0530x; 1.0317x over previous
#include <cuda_runtime.h>
#include <cstdint>

#define T_TOK 8192
#define IN_F  2048
#define OUT_F 2048
#define THRESH 6.0f
#define MAXOUT 64

// ---------------- device scratch ----------------
__device__ int8_t   g_wq[(size_t)OUT_F * IN_F];   // 4 MB
__device__ float    g_wscale[OUT_F];
__device__ int8_t   g_xq[(size_t)T_TOK * IN_F];   // 16 MB
__device__ float    g_xscale[T_TOK];
__device__ unsigned g_colmax[IN_F];
__device__ int      g_outidx[IN_F];
__device__ int      g_colrank[IN_F];
__device__ int      g_nout;
__device__ float    g_xout[(size_t)T_TOK * MAXOUT];   // 2 MB packed outlier x
__device__ float    g_wout[(size_t)OUT_F * MAXOUT];   // 512 KB packed outlier wq

// ---------------- prep ----------------
__global__ void k_init() {
    int i = blockIdx.x * 256 + threadIdx.x;
    if (i < IN_F) g_colmax[i] = 0u;
}

__device__ __forceinline__ float block_reduce_max(float v, float* sh) {
#pragma unroll
    for (int o = 16; o > 0; o >>= 1) v = fmaxf(v, __shfl_xor_sync(0xffffffffu, v, o));
    int w = threadIdx.x >> 5;
    if ((threadIdx.x & 31) == 0) sh[w] = v;
    __syncthreads();
    float r = sh[0];
#pragma unroll
    for (int i = 1; i < 8; ++i) r = fmaxf(r, sh[i]);
    return r;
}

__device__ __forceinline__ void quant8(const float* v, float s, int8_t* q8) {
#pragma unroll
    for (int k = 0; k < 8; ++k) {
        float q = rintf(v[k] * s);
        q = fminf(fmaxf(q, -127.f), 127.f);
        q8[k] = (int8_t)q;
    }
}

// fused: blocks [0,512) column absmax of x (vectorized, high-MLP);
//        blocks [512,2560) row quant of w (float4 + packed stores)
__global__ void k_cq(const float* __restrict__ x, const float* __restrict__ w) {
    __shared__ float4 sh4[256];
    __shared__ float sh[8];
    const int tid = threadIdx.x;
    if (blockIdx.x < 512) {
        // 64 row-slabs (128 rows) x 8 col-groups (256 cols = 64 float4)
        const int slab = blockIdx.x >> 3;          // 0..63
        const int cg   = blockIdx.x & 7;           // 0..7
        const int f4c  = tid & 63;                 // float4 col within group
        const int rsub = tid >> 6;                 // 0..3 -> 32 rows each
        const float4* p = reinterpret_cast<const float4*>(x)
                        + (size_t)(slab * 128 + rsub * 32) * (IN_F / 4) + cg * 64 + f4c;
        float4 m = make_float4(0.f, 0.f, 0.f, 0.f);
#pragma unroll 8
        for (int r = 0; r < 32; ++r) {
            float4 v = p[(size_t)r * (IN_F / 4)];
            m.x = fmaxf(m.x, fabsf(v.x)); m.y = fmaxf(m.y, fabsf(v.y));
            m.z = fmaxf(m.z, fabsf(v.z)); m.w = fmaxf(m.w, fabsf(v.w));
        }
        sh4[tid] = m;
        __syncthreads();
        if (tid < 64) {
            float4 a = sh4[tid], b = sh4[tid + 64], c = sh4[tid + 128], d = sh4[tid + 192];
            a.x = fmaxf(fmaxf(a.x, b.x), fmaxf(c.x, d.x));
            a.y = fmaxf(fmaxf(a.y, b.y), fmaxf(c.y, d.y));
            a.z = fmaxf(fmaxf(a.z, b.z), fmaxf(c.z, d.z));
            a.w = fmaxf(fmaxf(a.w, b.w), fmaxf(c.w, d.w));
            int c0 = cg * 256 + tid * 4;
            atomicMax(&g_colmax[c0 + 0], __float_as_uint(a.x));
            atomicMax(&g_colmax[c0 + 1], __float_as_uint(a.y));
            atomicMax(&g_colmax[c0 + 2], __float_as_uint(a.z));
            atomicMax(&g_colmax[c0 + 3], __float_as_uint(a.w));
        }
    } else {
        const int row = blockIdx.x - 512;
        const float4* wr = reinterpret_cast<const float4*>(w + (size_t)row * IN_F) + tid * 2;
        float4 v0 = wr[0], v1 = wr[1];
        float v[8] = { v0.x, v0.y, v0.z, v0.w, v1.x, v1.y, v1.z, v1.w };
        float m = 0.f;
#pragma unroll
        for (int k = 0; k < 8; ++k) m = fmaxf(m, fabsf(v[k]));
        float amax = fmaxf(block_reduce_max(m, sh), 1e-6f);
        float s = 127.0f / amax;
        int8_t q8[8];
        quant8(v, s, q8);
        *reinterpret_cast<int2*>(g_wq + (size_t)row * IN_F + tid * 8) =
            *reinterpret_cast<const int2*>(q8);
        if (tid == 0) g_wscale[row] = amax / 127.0f;
    }
}

// deterministic gather: 2048-bit mask + popc prefix ranks; also records colrank
__global__ void k_gather3() {
    __shared__ uint32_t mask[64];
    __shared__ int wpref[64];
    int tid = threadIdx.x, lane = tid & 31, w = tid >> 5;
#pragma unroll
    for (int it = 0; it < 8; ++it) {
        int wi = it * 8 + w;
        bool f = __uint_as_float(g_colmax[wi * 32 + lane]) > THRESH;
        uint32_t m = __ballot_sync(0xffffffffu, f);
        if (lane == 0) mask[wi] = m;
    }
    __syncthreads();
    if (tid < 64) {
        int s = 0;
        for (int k = 0; k < tid; ++k) s += __popc(mask[k]);
        wpref[tid] = s;
    }
    __syncthreads();
#pragma unroll
    for (int it = 0; it < 8; ++it) {
        int c = it * 256 + tid;
        uint32_t m = mask[c >> 5];
        if (m & (1u << (c & 31))) {
            int r = wpref[c >> 5] + __popc(m & ((1u << (c & 31)) - 1u));
            g_outidx[r] = c;
            g_colrank[c] = r;
        }
    }
    if (tid == 0) g_nout = wpref[63] + __popc(mask[63]);
}

// fused: blocks [0,8192) quantx (vectorized) + pack own token's outlier row;
//        blocks [8192,8704) pack w outlier columns
__global__ void k_qp(const float* __restrict__ x) {
    __shared__ float sh[8];
    const int tid = threadIdx.x;
    if (blockIdx.x < T_TOK) {
        const int t = blockIdx.x;
        if (tid < MAXOUT) g_xout[(size_t)t * MAXOUT + tid] = 0.f;
        __syncthreads();
        const float4* xr = reinterpret_cast<const float4*>(x + (size_t)t * IN_F) + tid * 2;
        float4 v0 = xr[0], v1 = xr[1];
        float v[8] = { v0.x, v0.y, v0.z, v0.w, v1.x, v1.y, v1.z, v1.w };
        const int c0 = tid * 8;
        float m = 0.f;
#pragma unroll
        for (int k = 0; k < 8; ++k) {
            if (__uint_as_float(g_colmax[c0 + k]) > THRESH) {
                int r = g_colrank[c0 + k];
                if (r < MAXOUT) g_xout[(size_t)t * MAXOUT + r] = v[k];
                v[k] = 0.f;
            }
            m = fmaxf(m, fabsf(v[k]));
        }
        float amax = fmaxf(block_reduce_max(m, sh), 1e-6f);
        float s = 127.0f / amax;
        int8_t q8[8];
        quant8(v, s, q8);
        *reinterpret_cast<int2*>(g_xq + (size_t)t * IN_F + c0) =
            *reinterpret_cast<const int2*>(q8);
        if (tid == 0) g_xscale[t] = amax / 127.0f;
    } else {
        int j = (blockIdx.x - T_TOK) * 256 + tid;     // [0, OUT_F*64)
        int o = j >> 6, s = j & 63;
        int nout = g_nout; if (nout > MAXOUT) nout = MAXOUT;
        float v = 0.f;
        if (s < nout) v = (float)g_wq[(size_t)o * IN_F + g_outidx[s]];
        g_wout[j] = v;
    }
}

// ---------------- DP4A GEMM: BM=BN=128, BK=128, cp.async 2-stage, SW128 (proven) ----------------
#define NTILES 16

__device__ __forceinline__ uint32_t swz128(uint32_t off) { return off ^ ((off >> 3) & 0x70); }

__device__ __forceinline__ uint32_t smem_u32(const void* p) {
    uint32_t a;
    asm("{ .reg .u64 t; cvta.to.shared.u64 t, %1; cvt.u32.u64 %0, t; }" : "=r"(a) : "l"(p));
    return a;
}
__device__ __forceinline__ void cpa16(uint32_t dst, const void* src) {
    asm volatile("cp.async.cg.shared.global [%0], [%1], 16;" :: "r"(dst), "l"(src));
}
#define CP_COMMIT() asm volatile("cp.async.commit_group;" ::: "memory")
#define CP_WAIT0()  asm volatile("cp.async.wait_group 0;" ::: "memory")

__device__ __forceinline__ int dp4(uint32_t a, uint32_t b, int c) {
    return __dp4a((int)a, (int)b, c);
}

__global__ __launch_bounds__(256, 2) void k_gemm(const float* __restrict__ bias,
                                                 float* __restrict__ out) {
    extern __shared__ char sm[];
    const uint32_t sbase = smem_u32(sm);
    const int tid = threadIdx.x;
    const int tx = tid & 15;
    const int ty = tid >> 4;
    const int m_blk = blockIdx.y * 128;
    const int n_blk = blockIdx.x * 128;

    const int lrow = tid >> 3;
    const int lq = tid & 7;
    const uint32_t sto = swz128((uint32_t)(lrow * 128 + lq * 16));

    int acc[8][8];
#pragma unroll
    for (int i = 0; i < 8; ++i)
#pragma unroll
        for (int j = 0; j < 8; ++j) acc[i][j] = 0;

    {
        const int8_t* ga = g_xq + (size_t)(m_blk + lrow) * IN_F + lq * 16;
        const int8_t* gb = g_wq + (size_t)(n_blk + lrow) * IN_F + lq * 16;
#pragma unroll
        for (int i = 0; i < 4; ++i) {
            cpa16(sbase + sto + i * (32 * 128),         ga + (size_t)i * 32 * IN_F);
            cpa16(sbase + 32768 + sto + i * (32 * 128), gb + (size_t)i * 32 * IN_F);
        }
        CP_COMMIT(); CP_WAIT0();
    }
    __syncthreads();

#pragma unroll 1
    for (int t = 0; t < NTILES; ++t) {
        const int buf = t & 1;
        const bool more = (t + 1) < NTILES;
        if (more) {
            const int nb = buf ^ 1;
            const size_t kof = (size_t)(t + 1) * 128 + lq * 16;
            const int8_t* ga = g_xq + (size_t)(m_blk + lrow) * IN_F + kof;
            const int8_t* gb = g_wq + (size_t)(n_blk + lrow) * IN_F + kof;
#pragma unroll
            for (int i = 0; i < 4; ++i) {
                cpa16(sbase + nb * 16384 + sto + i * (32 * 128),         ga + (size_t)i * 32 * IN_F);
                cpa16(sbase + 32768 + nb * 16384 + sto + i * (32 * 128), gb + (size_t)i * 32 * IN_F);
            }
            CP_COMMIT();
        }
        const char* aS = sm + buf * 16384;
        const char* bS = sm + 32768 + buf * 16384;
#pragma unroll
        for (int kk = 0; kk < 8; ++kk) {
            uint4 bf[8];
#pragma unroll
            for (int j = 0; j < 8; ++j)
                bf[j] = *reinterpret_cast<const uint4*>(bS + swz128((uint32_t)((tx + j * 16) * 128 + kk * 16)));
#pragma unroll
            for (int i = 0; i < 8; ++i) {
                uint4 a = *reinterpret_cast<const uint4*>(aS + swz128((uint32_t)((ty * 8 + i) * 128 + kk * 16)));
#pragma unroll
                for (int j = 0; j < 8; ++j) {
                    acc[i][j] = dp4(a.x, bf[j].x, acc[i][j]);
                    acc[i][j] = dp4(a.y, bf[j].y, acc[i][j]);
                    acc[i][j] = dp4(a.z, bf[j].z, acc[i][j]);
                    acc[i][j] = dp4(a.w, bf[j].w, acc[i][j]);
                }
            }
        }
        if (more) CP_WAIT0();
        __syncthreads();
    }

    float xs[8], ws[8], bs[8];
#pragma unroll
    for (int i = 0; i < 8; ++i) xs[i] = g_xscale[m_blk + ty * 8 + i];
#pragma unroll
    for (int j = 0; j < 8; ++j) {
        int gn = n_blk + tx + j * 16;
        ws[j] = g_wscale[gn];
        bs[j] = bias[gn];
    }

    float facc[8][8];
#pragma unroll
    for (int i = 0; i < 8; ++i)
#pragma unroll
        for (int j = 0; j < 8; ++j) facc[i][j] = xs[i] * (float)acc[i][j];

    float* xo = reinterpret_cast<float*>(sm);            // [128][17]
    float* wo = reinterpret_cast<float*>(sm + 8704);     // [128][17]

    int nout = g_nout; if (nout > MAXOUT) nout = MAXOUT;
    for (int base = 0; base < nout; base += 16) {
        for (int idx = tid; idx < 128 * 16; idx += 256) {
            int r = idx >> 4, c = idx & 15;
            xo[r * 17 + c] = g_xout[(size_t)(m_blk + r) * MAXOUT + base + c];
            wo[r * 17 + c] = g_wout[(size_t)(n_blk + r) * MAXOUT + base + c];
        }
        __syncthreads();
#pragma unroll
        for (int c = 0; c < 16; ++c) {
            float xa[8], wb[8];
#pragma unroll
            for (int i = 0; i < 8; ++i) xa[i] = xo[(ty * 8 + i) * 17 + c];
#pragma unroll
            for (int j = 0; j < 8; ++j) wb[j] = wo[(tx + j * 16) * 17 + c];
#pragma unroll
            for (int i = 0; i < 8; ++i)
#pragma unroll
                for (int j = 0; j < 8; ++j) facc[i][j] += xa[i] * wb[j];
        }
        __syncthreads();
    }

#pragma unroll
    for (int i = 0; i < 8; ++i) {
        size_t gm = m_blk + ty * 8 + i;
#pragma unroll
        for (int j = 0; j < 8; ++j) {
            int gn = n_blk + tx + j * 16;
            out[gm * OUT_F + gn] = ws[j] * facc[i][j] + bs[j];
        }
    }
}

// ---------------- launch ----------------
extern "C" void kernel_launch(void* const* d_in, const int* in_sizes, int n_in,
                              void* d_out, int out_size) {
    const float* x    = (const float*)d_in[0];
    const float* w    = (const float*)d_in[1];
    const float* bias = (const float*)d_in[2];
    float* out = (float*)d_out;

    cudaFuncSetAttribute(k_gemm, cudaFuncAttributeMaxDynamicSharedMemorySize, 65536);

    k_init<<<8, 256>>>();
    k_cq<<<512 + OUT_F, 256>>>(x, w);
    k_gather3<<<1, 256>>>();
    k_qp<<<T_TOK + OUT_F * MAXOUT / 256, 256>>>(x);
    k_gemm<<<dim3(OUT_F / 128, T_TOK / 128), 256, 65536>>>(bias, out);
}

// round 17
// speedup vs baseline: 1.0722x; 1.0182x over previous
#include <cuda_runtime.h>
#include <cstdint>

#define T_TOK 8192
#define IN_F  2048
#define OUT_F 2048
#define THRESH 6.0f
#define MAXOUT 64

// ---------------- device scratch ----------------
__device__ int8_t   g_wq[(size_t)OUT_F * IN_F];   // 4 MB
__device__ float    g_wscale[OUT_F];
__device__ int8_t   g_xq[(size_t)T_TOK * IN_F];   // 16 MB
__device__ float    g_xscale[T_TOK];
__device__ unsigned g_colmax[IN_F];
__device__ uint32_t g_colmask[IN_F / 32];         // outlier bitmap
__device__ int      g_outidx[IN_F];
__device__ int      g_colrank[IN_F];
__device__ int      g_nout;
__device__ float    g_xout[(size_t)T_TOK * MAXOUT];   // 2 MB packed outlier x
__device__ float    g_wout[(size_t)OUT_F * MAXOUT];   // 512 KB packed outlier wq

// ---------------- prep ----------------
__global__ void k_init() {
    int i = blockIdx.x * 256 + threadIdx.x;
    if (i < IN_F) g_colmax[i] = 0u;
}

__device__ __forceinline__ float warp_max(float v) {
#pragma unroll
    for (int o = 16; o > 0; o >>= 1) v = fmaxf(v, __shfl_xor_sync(0xffffffffu, v, o));
    return v;
}

// NOTE: plain `char` is UNSIGNED on the aarch64 host ABI — must cast via int -> signed char.
__device__ __forceinline__ char4 quant4(float4 v, float s) {
    char4 q;
    q.x = (signed char)(int)fminf(fmaxf(rintf(v.x * s), -127.f), 127.f);
    q.y = (signed char)(int)fminf(fmaxf(rintf(v.y * s), -127.f), 127.f);
    q.z = (signed char)(int)fminf(fmaxf(rintf(v.z * s), -127.f), 127.f);
    q.w = (signed char)(int)fminf(fmaxf(rintf(v.w * s), -127.f), 127.f);
    return q;
}

// fused: blocks [0,512) column absmax of x (high-MLP);
//        blocks [512,1024) row quant of w: 4 rows/block, 64 thr/row, MLP=8
__global__ void k_cq(const float* __restrict__ x, const float* __restrict__ w) {
    __shared__ float4 sh4[256];
    __shared__ float sred[8];
    const int tid = threadIdx.x;
    if (blockIdx.x < 512) {
        const int slab = blockIdx.x >> 3;
        const int cg   = blockIdx.x & 7;
        const int f4c  = tid & 63;
        const int rsub = tid >> 6;
        const float4* p = reinterpret_cast<const float4*>(x)
                        + (size_t)(slab * 128 + rsub * 32) * (IN_F / 4) + cg * 64 + f4c;
        float4 m = make_float4(0.f, 0.f, 0.f, 0.f);
#pragma unroll 8
        for (int r = 0; r < 32; ++r) {
            float4 v = p[(size_t)r * (IN_F / 4)];
            m.x = fmaxf(m.x, fabsf(v.x)); m.y = fmaxf(m.y, fabsf(v.y));
            m.z = fmaxf(m.z, fabsf(v.z)); m.w = fmaxf(m.w, fabsf(v.w));
        }
        sh4[tid] = m;
        __syncthreads();
        if (tid < 64) {
            float4 a = sh4[tid], b = sh4[tid + 64], c = sh4[tid + 128], d = sh4[tid + 192];
            a.x = fmaxf(fmaxf(a.x, b.x), fmaxf(c.x, d.x));
            a.y = fmaxf(fmaxf(a.y, b.y), fmaxf(c.y, d.y));
            a.z = fmaxf(fmaxf(a.z, b.z), fmaxf(c.z, d.z));
            a.w = fmaxf(fmaxf(a.w, b.w), fmaxf(c.w, d.w));
            int c0 = cg * 256 + tid * 4;
            atomicMax(&g_colmax[c0 + 0], __float_as_uint(a.x));
            atomicMax(&g_colmax[c0 + 1], __float_as_uint(a.y));
            atomicMax(&g_colmax[c0 + 2], __float_as_uint(a.z));
            atomicMax(&g_colmax[c0 + 3], __float_as_uint(a.w));
        }
    } else {
        const int g = tid >> 6, l = tid & 63, wsub = (tid >> 5) & 1;
        const int row = (blockIdx.x - 512) * 4 + g;
        const float4* wr = reinterpret_cast<const float4*>(w) + (size_t)row * (IN_F / 4) + l;
        float4 v[8];
#pragma unroll
        for (int i = 0; i < 8; ++i) v[i] = wr[i * 64];
        float m = 0.f;
#pragma unroll
        for (int i = 0; i < 8; ++i)
            m = fmaxf(m, fmaxf(fmaxf(fabsf(v[i].x), fabsf(v[i].y)),
                               fmaxf(fabsf(v[i].z), fabsf(v[i].w))));
        m = warp_max(m);
        if ((tid & 31) == 0) sred[g * 2 + wsub] = m;
        __syncthreads();
        float amax = fmaxf(fmaxf(sred[g * 2], sred[g * 2 + 1]), 1e-6f);
        float s = 127.0f / amax;
        char4* dst = reinterpret_cast<char4*>(g_wq) + (size_t)row * (IN_F / 4) + l;
#pragma unroll
        for (int i = 0; i < 8; ++i) dst[i * 64] = quant4(v[i], s);
        if (l == 0) g_wscale[row] = amax / 127.0f;
    }
}

// deterministic gather: 2048-bit mask + popc prefix ranks; exports mask + colrank
__global__ void k_gather3() {
    __shared__ uint32_t mask[64];
    __shared__ int wpref[64];
    int tid = threadIdx.x, lane = tid & 31, w = tid >> 5;
#pragma unroll
    for (int it = 0; it < 8; ++it) {
        int wi = it * 8 + w;
        bool f = __uint_as_float(g_colmax[wi * 32 + lane]) > THRESH;
        uint32_t m = __ballot_sync(0xffffffffu, f);
        if (lane == 0) mask[wi] = m;
    }
    __syncthreads();
    if (tid < 64) {
        g_colmask[tid] = mask[tid];
        int s = 0;
        for (int k = 0; k < tid; ++k) s += __popc(mask[k]);
        wpref[tid] = s;
    }
    __syncthreads();
#pragma unroll
    for (int it = 0; it < 8; ++it) {
        int c = it * 256 + tid;
        uint32_t m = mask[c >> 5];
        if (m & (1u << (c & 31))) {
            int r = wpref[c >> 5] + __popc(m & ((1u << (c & 31)) - 1u));
            g_outidx[r] = c;
            g_colrank[c] = r;
        }
    }
    if (tid == 0) g_nout = wpref[63] + __popc(mask[63]);
}

// fused: blocks [0,2048): quantx+pack, 4 tokens/block, 64 thr/token, MLP=8;
//        blocks [2048,2560): pack w outlier columns
__global__ void k_qp(const float* __restrict__ x) {
    __shared__ uint32_t smask[64];
    __shared__ float sred[8];
    const int tid = threadIdx.x;
    if (blockIdx.x < T_TOK / 4) {
        const int g = tid >> 6, l = tid & 63, wsub = (tid >> 5) & 1;
        const int t = blockIdx.x * 4 + g;
        if (tid < 64) smask[tid] = g_colmask[tid];
        g_xout[(size_t)blockIdx.x * 4 * MAXOUT + tid] = 0.f;   // zero 4 tokens x 64
        __syncthreads();
        const float4* xr = reinterpret_cast<const float4*>(x) + (size_t)t * (IN_F / 4) + l;
        float4 v[8];
#pragma unroll
        for (int i = 0; i < 8; ++i) v[i] = xr[i * 64];
        float m = 0.f;
#pragma unroll
        for (int i = 0; i < 8; ++i) {
            const int c = (l + i * 64) * 4;
            float* pv = &v[i].x;
#pragma unroll
            for (int k = 0; k < 4; ++k) {
                uint32_t mk = smask[(c + k) >> 5];
                if (mk & (1u << ((c + k) & 31))) {
                    int r = g_colrank[c + k];
                    if (r < MAXOUT) g_xout[(size_t)t * MAXOUT + r] = pv[k];
                    pv[k] = 0.f;
                }
                m = fmaxf(m, fabsf(pv[k]));
            }
        }
        m = warp_max(m);
        if ((tid & 31) == 0) sred[g * 2 + wsub] = m;
        __syncthreads();
        float amax = fmaxf(fmaxf(sred[g * 2], sred[g * 2 + 1]), 1e-6f);
        float s = 127.0f / amax;
        char4* dst = reinterpret_cast<char4*>(g_xq) + (size_t)t * (IN_F / 4) + l;
#pragma unroll
        for (int i = 0; i < 8; ++i) dst[i * 64] = quant4(v[i], s);
        if (l == 0) g_xscale[t] = amax / 127.0f;
    } else {
        int j = (blockIdx.x - T_TOK / 4) * 256 + tid;     // [0, OUT_F*64)
        int o = j >> 6, s = j & 63;
        int nout = g_nout; if (nout > MAXOUT) nout = MAXOUT;
        float v = 0.f;
        if (s < nout) v = (float)g_wq[(size_t)o * IN_F + g_outidx[s]];
        g_wout[j] = v;
    }
}

// ---------------- DP4A GEMM: BM=BN=128, BK=128, cp.async 2-stage, SW128 (proven) ----------------
#define NTILES 16

__device__ __forceinline__ uint32_t swz128(uint32_t off) { return off ^ ((off >> 3) & 0x70); }

__device__ __forceinline__ uint32_t smem_u32(const void* p) {
    uint32_t a;
    asm("{ .reg .u64 t; cvta.to.shared.u64 t, %1; cvt.u32.u64 %0, t; }" : "=r"(a) : "l"(p));
    return a;
}
__device__ __forceinline__ void cpa16(uint32_t dst, const void* src) {
    asm volatile("cp.async.cg.shared.global [%0], [%1], 16;" :: "r"(dst), "l"(src));
}
#define CP_COMMIT() asm volatile("cp.async.commit_group;" ::: "memory")
#define CP_WAIT0()  asm volatile("cp.async.wait_group 0;" ::: "memory")

__device__ __forceinline__ int dp4(uint32_t a, uint32_t b, int c) {
    return __dp4a((int)a, (int)b, c);
}

__global__ __launch_bounds__(256, 2) void k_gemm(const float* __restrict__ bias,
                                                 float* __restrict__ out) {
    extern __shared__ char sm[];
    const uint32_t sbase = smem_u32(sm);
    const int tid = threadIdx.x;
    const int tx = tid & 15;
    const int ty = tid >> 4;
    const int m_blk = blockIdx.y * 128;
    const int n_blk = blockIdx.x * 128;

    const int lrow = tid >> 3;
    const int lq = tid & 7;
    const uint32_t sto = swz128((uint32_t)(lrow * 128 + lq * 16));

    int acc[8][8];
#pragma unroll
    for (int i = 0; i < 8; ++i)
#pragma unroll
        for (int j = 0; j < 8; ++j) acc[i][j] = 0;

    {
        const int8_t* ga = g_xq + (size_t)(m_blk + lrow) * IN_F + lq * 16;
        const int8_t* gb = g_wq + (size_t)(n_blk + lrow) * IN_F + lq * 16;
#pragma unroll
        for (int i = 0; i < 4; ++i) {
            cpa16(sbase + sto + i * (32 * 128),         ga + (size_t)i * 32 * IN_F);
            cpa16(sbase + 32768 + sto + i * (32 * 128), gb + (size_t)i * 32 * IN_F);
        }
        CP_COMMIT(); CP_WAIT0();
    }
    __syncthreads();

#pragma unroll 1
    for (int t = 0; t < NTILES; ++t) {
        const int buf = t & 1;
        const bool more = (t + 1) < NTILES;
        if (more) {
            const int nb = buf ^ 1;
            const size_t kof = (size_t)(t + 1) * 128 + lq * 16;
            const int8_t* ga = g_xq + (size_t)(m_blk + lrow) * IN_F + kof;
            const int8_t* gb = g_wq + (size_t)(n_blk + lrow) * IN_F + kof;
#pragma unroll
            for (int i = 0; i < 4; ++i) {
                cpa16(sbase + nb * 16384 + sto + i * (32 * 128),         ga + (size_t)i * 32 * IN_F);
                cpa16(sbase + 32768 + nb * 16384 + sto + i * (32 * 128), gb + (size_t)i * 32 * IN_F);
            }
            CP_COMMIT();
        }
        const char* aS = sm + buf * 16384;
        const char* bS = sm + 32768 + buf * 16384;
#pragma unroll
        for (int kk = 0; kk < 8; ++kk) {
            uint4 bf[8];
#pragma unroll
            for (int j = 0; j < 8; ++j)
                bf[j] = *reinterpret_cast<const uint4*>(bS + swz128((uint32_t)((tx + j * 16) * 128 + kk * 16)));
#pragma unroll
            for (int i = 0; i < 8; ++i) {
                uint4 a = *reinterpret_cast<const uint4*>(aS + swz128((uint32_t)((ty * 8 + i) * 128 + kk * 16)));
#pragma unroll
                for (int j = 0; j < 8; ++j) {
                    acc[i][j] = dp4(a.x, bf[j].x, acc[i][j]);
                    acc[i][j] = dp4(a.y, bf[j].y, acc[i][j]);
                    acc[i][j] = dp4(a.z, bf[j].z, acc[i][j]);
                    acc[i][j] = dp4(a.w, bf[j].w, acc[i][j]);
                }
            }
        }
        if (more) CP_WAIT0();
        __syncthreads();
    }

    float xs[8], ws[8], bs[8];
#pragma unroll
    for (int i = 0; i < 8; ++i) xs[i] = g_xscale[m_blk + ty * 8 + i];
#pragma unroll
    for (int j = 0; j < 8; ++j) {
        int gn = n_blk + tx + j * 16;
        ws[j] = g_wscale[gn];
        bs[j] = bias[gn];
    }

    float facc[8][8];
#pragma unroll
    for (int i = 0; i < 8; ++i)
#pragma unroll
        for (int j = 0; j < 8; ++j) facc[i][j] = xs[i] * (float)acc[i][j];

    float* xo = reinterpret_cast<float*>(sm);            // [128][17]
    float* wo = reinterpret_cast<float*>(sm + 8704);     // [128][17]

    int nout = g_nout; if (nout > MAXOUT) nout = MAXOUT;
    for (int base = 0; base < nout; base += 16) {
        for (int idx = tid; idx < 128 * 16; idx += 256) {
            int r = idx >> 4, c = idx & 15;
            xo[r * 17 + c] = g_xout[(size_t)(m_blk + r) * MAXOUT + base + c];
            wo[r * 17 + c] = g_wout[(size_t)(n_blk + r) * MAXOUT + base + c];
        }
        __syncthreads();
#pragma unroll
        for (int c = 0; c < 16; ++c) {
            float xa[8], wb[8];
#pragma unroll
            for (int i = 0; i < 8; ++i) xa[i] = xo[(ty * 8 + i) * 17 + c];
#pragma unroll
            for (int j = 0; j < 8; ++j) wb[j] = wo[(tx + j * 16) * 17 + c];
#pragma unroll
            for (int i = 0; i < 8; ++i)
#pragma unroll
                for (int j = 0; j < 8; ++j) facc[i][j] += xa[i] * wb[j];
        }
        __syncthreads();
    }

#pragma unroll
    for (int i = 0; i < 8; ++i) {
        size_t gm = m_blk + ty * 8 + i;
#pragma unroll
        for (int j = 0; j < 8; ++j) {
            int gn = n_blk + tx + j * 16;
            out[gm * OUT_F + gn] = ws[j] * facc[i][j] + bs[j];
        }
    }
}

// ---------------- launch ----------------
extern "C" void kernel_launch(void* const* d_in, const int* in_sizes, int n_in,
                              void* d_out, int out_size) {
    const float* x    = (const float*)d_in[0];
    const float* w    = (const float*)d_in[1];
    const float* bias = (const float*)d_in[2];
    float* out = (float*)d_out;

    cudaFuncSetAttribute(k_gemm, cudaFuncAttributeMaxDynamicSharedMemorySize, 65536);

    k_init<<<8, 256>>>();
    k_cq<<<512 + OUT_F / 4, 256>>>(x, w);
    k_gather3<<<1, 256>>>();
    k_qp<<<T_TOK / 4 + (OUT_F * MAXOUT) / 256, 256>>>(x);
    k_gemm<<<dim3(OUT_F / 128, T_TOK / 128), 256, 65536>>>(bias, out);
}